// round 5
// baseline (speedup 1.0000x reference)
#include <cuda_runtime.h>
#include <cfloat>
#include <math.h>

#define Nn 50000
#define Ee 800000
#define EF 850000     // Ee + Nn self loops
#define FIN 64
#define EDIM 16
#define Hh 4
#define Cc 32
#define HC 128
#define Bb 64
#define Aa 8
#define NB_SCAN ((Nn + 255) / 256)   // 196

// ---------------- scratch ----------------
__device__ float g_xw[Nn * HC];
__device__ float g_hA[Nn * HC];
__device__ float g_hB[Nn * HC];
__device__ int   g_cnt[Nn];
__device__ int   g_fill[Nn];
__device__ int   g_rowptr[Nn + 1];
__device__ int   g_bsum[256];
__device__ int   g_boff[256];
__device__ int   g_psrc[EF];
__device__ float g_pattr[(size_t)EF * EDIM];   // CSR-permuted edge attrs (+ self-loop mean rows)
__device__ float g_scs[Nn * Hh];
__device__ float g_scd[Nn * Hh];
__device__ float g_gsum[Bb * HC];
__device__ int   g_gcnt[Bb];

// ---------------- helpers ----------------
__device__ __forceinline__ float lrelu(float v) { return v > 0.f ? v : 0.2f * v; }

__device__ __forceinline__ float4 wmax4(float4 v) {
#pragma unroll
    for (int o = 16; o; o >>= 1) {
        v.x = fmaxf(v.x, __shfl_xor_sync(0xffffffffu, v.x, o));
        v.y = fmaxf(v.y, __shfl_xor_sync(0xffffffffu, v.y, o));
        v.z = fmaxf(v.z, __shfl_xor_sync(0xffffffffu, v.z, o));
        v.w = fmaxf(v.w, __shfl_xor_sync(0xffffffffu, v.w, o));
    }
    return v;
}
__device__ __forceinline__ float4 wsum4(float4 v) {
#pragma unroll
    for (int o = 16; o; o >>= 1) {
        v.x += __shfl_xor_sync(0xffffffffu, v.x, o);
        v.y += __shfl_xor_sync(0xffffffffu, v.y, o);
        v.z += __shfl_xor_sync(0xffffffffu, v.z, o);
        v.w += __shfl_xor_sync(0xffffffffu, v.w, o);
    }
    return v;
}

// sce for edge slot e computed inline from CSR-ordered pattr (coalesced)
__device__ __forceinline__ float4 sce_of(const float* __restrict__ ve, int e) {
    const float* ap = g_pattr + (size_t)e * EDIM;
    float h0 = 0.f, h1 = 0.f, h2 = 0.f, h3 = 0.f;
#pragma unroll
    for (int q = 0; q < 4; q++) {
        float4 av = *(const float4*)(ap + q * 4);
        int d = q * 4;
        h0 += av.x * ve[d * 4 + 0] + av.y * ve[(d + 1) * 4 + 0] + av.z * ve[(d + 2) * 4 + 0] + av.w * ve[(d + 3) * 4 + 0];
        h1 += av.x * ve[d * 4 + 1] + av.y * ve[(d + 1) * 4 + 1] + av.z * ve[(d + 2) * 4 + 1] + av.w * ve[(d + 3) * 4 + 1];
        h2 += av.x * ve[d * 4 + 2] + av.y * ve[(d + 1) * 4 + 2] + av.z * ve[(d + 2) * 4 + 2] + av.w * ve[(d + 3) * 4 + 2];
        h3 += av.x * ve[d * 4 + 3] + av.y * ve[(d + 1) * 4 + 3] + av.z * ve[(d + 2) * 4 + 3] + av.w * ve[(d + 3) * 4 + 3];
    }
    return make_float4(h0, h1, h2, h3);
}

__device__ __forceinline__ float4 raw_score(const float* __restrict__ ve, int src, int e, float4 sd) {
    float4 ss = *(const float4*)(g_scs + src * 4);
    float4 se = sce_of(ve, e);
    float4 r;
    r.x = lrelu(ss.x + sd.x + se.x);
    r.y = lrelu(ss.y + sd.y + se.y);
    r.z = lrelu(ss.z + sd.z + se.z);
    r.w = lrelu(ss.w + sd.w + se.w);
    return r;
}

// ---------------- preprocessing ----------------
__global__ void k_init() {
    int i = blockIdx.x * blockDim.x + threadIdx.x;
    if (i < Nn) { g_cnt[i] = 0; g_fill[i] = 0; }
    if (i < Bb * HC) g_gsum[i] = 0.f;
    if (i < Bb) g_gcnt[i] = 0;
}

__global__ void k_count(const int* __restrict__ ei) {
    int e = blockIdx.x * blockDim.x + threadIdx.x;
    if (e >= Ee) return;
    atomicAdd(&g_cnt[ei[Ee + e]], 1);
}

__global__ void k_scan1() {
    __shared__ int sh[256];
    int t = threadIdx.x;
    int i = blockIdx.x * 256 + t;
    int v = (i < Nn) ? (g_cnt[i] + 1) : 0;
    sh[t] = v;
    __syncthreads();
#pragma unroll
    for (int o = 1; o < 256; o <<= 1) {
        int u = (t >= o) ? sh[t - o] : 0;
        __syncthreads();
        sh[t] += u;
        __syncthreads();
    }
    if (i < Nn) g_rowptr[i] = sh[t] - v;
    if (t == 255) g_bsum[blockIdx.x] = sh[255];
}

__global__ void k_scan2() {
    __shared__ int sh[256];
    int t = threadIdx.x;
    int v = (t < NB_SCAN) ? g_bsum[t] : 0;
    sh[t] = v;
    __syncthreads();
#pragma unroll
    for (int o = 1; o < 256; o <<= 1) {
        int u = (t >= o) ? sh[t - o] : 0;
        __syncthreads();
        sh[t] += u;
        __syncthreads();
    }
    if (t < NB_SCAN) g_boff[t] = sh[t] - v;
    if (t == 255) g_rowptr[Nn] = sh[255];
}

__global__ void k_scan3() {
    int i = blockIdx.x * 256 + threadIdx.x;
    if (i < Nn) g_rowptr[i] += g_boff[blockIdx.x];
}

// scatter psrc + permute edge_attr into CSR order
__global__ void k_scatter(const int* __restrict__ ei, const float* __restrict__ eattr) {
    int e = blockIdx.x * blockDim.x + threadIdx.x;
    if (e >= Ee) return;
    int s = ei[e], d = ei[Ee + e];
    int pos = g_rowptr[d] + atomicAdd(&g_fill[d], 1);
    g_psrc[pos] = s;
    const float4* sp = (const float4*)(eattr + (size_t)e * EDIM);
    float4* dp = (float4*)(g_pattr + (size_t)pos * EDIM);
    dp[0] = sp[0]; dp[1] = sp[1]; dp[2] = sp[2]; dp[3] = sp[3];
}

// per-node mean of real in-edge attrs -> self-loop slot; psrc self = n
__global__ void __launch_bounds__(256) k_meanattr() {
    int n = (blockIdx.x * 256 + threadIdx.x) >> 5;
    int lane = threadIdx.x & 31;
    if (n >= Nn) return;
    int s0 = g_rowptr[n], s1 = g_rowptr[n + 1] - 1;   // real edges [s0,s1)
    float4 acc = make_float4(0.f, 0.f, 0.f, 0.f);
    const float4* pa = (const float4*)g_pattr;
    for (int r = s0 + (lane >> 2); r < s1; r += 8) {
        float4 v = pa[(size_t)r * 4 + (lane & 3)];
        acc.x += v.x; acc.y += v.y; acc.z += v.z; acc.w += v.w;
    }
#pragma unroll
    for (int o = 4; o < 32; o <<= 1) {
        acc.x += __shfl_xor_sync(0xffffffffu, acc.x, o);
        acc.y += __shfl_xor_sync(0xffffffffu, acc.y, o);
        acc.z += __shfl_xor_sync(0xffffffffu, acc.z, o);
        acc.w += __shfl_xor_sync(0xffffffffu, acc.w, o);
    }
    if (lane < 4) {
        float ic = 1.0f / fmaxf((float)(s1 - s0), 1.0f);
        acc.x *= ic; acc.y *= ic; acc.z *= ic; acc.w *= ic;
        ((float4*)g_pattr)[(size_t)s1 * 4 + lane] = acc;
    }
    if (lane == 0) g_psrc[s1] = n;
}

// ---------------- per-layer ----------------
// GEMM + fused per-row attention score epilogue (scs/scd)
// inner loop: Xs cached in float4 regs per 4 k-steps -> LDS wavefronts halved
template <int K>
__global__ void __launch_bounds__(128) k_gemm(const float* __restrict__ A,
                                              const float* __restrict__ W,
                                              const float* __restrict__ a_s,
                                              const float* __restrict__ a_d,
                                              float* __restrict__ Out) {
    __shared__ float Ws[64][128];
    __shared__ float Xs[32][64];
    int tid = threadIdx.x;
    int tx = tid & 31, ty = tid >> 5;
    int rowbase = blockIdx.x * 32;
    float acc[8][4];
#pragma unroll
    for (int r = 0; r < 8; r++)
#pragma unroll
        for (int j = 0; j < 4; j++) acc[r][j] = 0.f;

    for (int kc = 0; kc < K; kc += 64) {
#pragma unroll
        for (int q = 0; q < 16; q++) {
            int idx = tid + 128 * q;
            int r = idx >> 5, c4 = idx & 31;
            *(float4*)&Ws[r][c4 * 4] = *(const float4*)&W[(size_t)(kc + r) * HC + c4 * 4];
        }
#pragma unroll
        for (int q = 0; q < 4; q++) {
            int idx = tid + 128 * q;
            int r = idx >> 4, c4 = idx & 15;
            int row = rowbase + r;
            float4 v = make_float4(0.f, 0.f, 0.f, 0.f);
            if (row < Nn) v = *(const float4*)&A[(size_t)row * K + kc + c4 * 4];
            *(float4*)&Xs[r][c4 * 4] = v;
        }
        __syncthreads();
#pragma unroll
        for (int k4 = 0; k4 < 64; k4 += 4) {
            float4 a4[8];
#pragma unroll
            for (int r = 0; r < 8; r++) a4[r] = *(const float4*)&Xs[ty + 4 * r][k4];
#pragma unroll
            for (int kk = 0; kk < 4; kk++) {
                float b0 = Ws[k4 + kk][tx];
                float b1 = Ws[k4 + kk][tx + 32];
                float b2 = Ws[k4 + kk][tx + 64];
                float b3 = Ws[k4 + kk][tx + 96];
#pragma unroll
                for (int r = 0; r < 8; r++) {
                    float a = (kk == 0) ? a4[r].x : (kk == 1) ? a4[r].y : (kk == 2) ? a4[r].z : a4[r].w;
                    acc[r][0] += a * b0;
                    acc[r][1] += a * b1;
                    acc[r][2] += a * b2;
                    acc[r][3] += a * b3;
                }
            }
        }
        __syncthreads();
    }

    float as0 = a_s[tx], as1 = a_s[32 + tx], as2 = a_s[64 + tx], as3 = a_s[96 + tx];
    float ad0 = a_d[tx], ad1 = a_d[32 + tx], ad2 = a_d[64 + tx], ad3 = a_d[96 + tx];

#pragma unroll
    for (int r = 0; r < 8; r++) {
        int row = rowbase + ty + 4 * r;
        if (row < Nn) {
#pragma unroll
            for (int j = 0; j < 4; j++) Out[(size_t)row * HC + tx + 32 * j] = acc[r][j];
            float4 ps = make_float4(acc[r][0] * as0, acc[r][1] * as1, acc[r][2] * as2, acc[r][3] * as3);
            float4 pd = make_float4(acc[r][0] * ad0, acc[r][1] * ad1, acc[r][2] * ad2, acc[r][3] * ad3);
            ps = wsum4(ps);
            pd = wsum4(pd);
            if (tx == 0) {
                *(float4*)(g_scs + row * 4) = ps;
                *(float4*)(g_scd + row * 4) = pd;
            }
        }
    }
}

// pick this lane's head weight from edge j's float4 weights
__device__ __forceinline__ float head_w(float4 wv, int j, int lane) {
    float wx = __shfl_sync(0xffffffffu, wv.x, j);
    float wy = __shfl_sync(0xffffffffu, wv.y, j);
    float wz = __shfl_sync(0xffffffffu, wv.z, j);
    float ww = __shfl_sync(0xffffffffu, wv.w, j);
    return lane < 16 ? (lane < 8 ? wx : wy) : (lane < 24 ? wz : ww);
}

// fused: edge scores (sce from pattr) + segment softmax + weighted gather
__global__ void __launch_bounds__(256) k_agg(const float* __restrict__ xw,
                                             const float* __restrict__ We,
                                             const float* __restrict__ ae,
                                             const float* __restrict__ bias,
                                             float* __restrict__ hout) {
    __shared__ float ve[EDIM * Hh];
    int t = threadIdx.x;
    if (t < EDIM * Hh) {
        int d = t >> 2, h = t & 3;
        float s = 0.f;
#pragma unroll
        for (int c = 0; c < Cc; c++) s += We[d * HC + h * Cc + c] * ae[h * Cc + c];
        ve[t] = s;
    }
    __syncthreads();

    int n = (blockIdx.x * 256 + t) >> 5;
    int lane = t & 31;
    if (n >= Nn) return;
    int s0 = g_rowptr[n], s1 = g_rowptr[n + 1];
    int deg = s1 - s0;
    float4 sd = *(const float4*)(g_scd + n * 4);
    float4 acc = make_float4(0.f, 0.f, 0.f, 0.f);

    if (deg <= 32) {
        int e = s0 + lane;
        bool v = e < s1;
        int srcv = 0;
        float4 raw = make_float4(-FLT_MAX, -FLT_MAX, -FLT_MAX, -FLT_MAX);
        if (v) {
            srcv = g_psrc[e];
            raw = raw_score(ve, srcv, e, sd);
        }
        float4 m = wmax4(raw);
        float4 a = make_float4(0.f, 0.f, 0.f, 0.f);
        if (v) {
            a.x = __expf(raw.x - m.x);
            a.y = __expf(raw.y - m.y);
            a.z = __expf(raw.z - m.z);
            a.w = __expf(raw.w - m.w);
        }
        float4 s = wsum4(a);
        float4 w;
        w.x = a.x / (s.x + 1e-16f);
        w.y = a.y / (s.y + 1e-16f);
        w.z = a.z / (s.z + 1e-16f);
        w.w = a.w / (s.w + 1e-16f);
        for (int j = 0; j < deg; j++) {
            int sj = __shfl_sync(0xffffffffu, srcv, j);
            float wsel = head_w(w, j, lane);
            float4 xr = *(const float4*)(xw + (size_t)sj * HC + lane * 4);
            acc.x += wsel * xr.x;
            acc.y += wsel * xr.y;
            acc.z += wsel * xr.z;
            acc.w += wsel * xr.w;
        }
    } else {
        float4 pm = make_float4(-FLT_MAX, -FLT_MAX, -FLT_MAX, -FLT_MAX);
        for (int base = s0; base < s1; base += 32) {
            int e = base + lane;
            if (e < s1) {
                float4 raw = raw_score(ve, g_psrc[e], e, sd);
                pm.x = fmaxf(pm.x, raw.x); pm.y = fmaxf(pm.y, raw.y);
                pm.z = fmaxf(pm.z, raw.z); pm.w = fmaxf(pm.w, raw.w);
            }
        }
        float4 m = wmax4(pm);
        float4 ps = make_float4(0.f, 0.f, 0.f, 0.f);
        for (int base = s0; base < s1; base += 32) {
            int e = base + lane;
            if (e < s1) {
                float4 raw = raw_score(ve, g_psrc[e], e, sd);
                ps.x += __expf(raw.x - m.x);
                ps.y += __expf(raw.y - m.y);
                ps.z += __expf(raw.z - m.z);
                ps.w += __expf(raw.w - m.w);
            }
        }
        float4 s = wsum4(ps);
        float4 rinv;
        rinv.x = 1.f / (s.x + 1e-16f);
        rinv.y = 1.f / (s.y + 1e-16f);
        rinv.z = 1.f / (s.z + 1e-16f);
        rinv.w = 1.f / (s.w + 1e-16f);
        for (int base = s0; base < s1; base += 32) {
            int e = base + lane;
            int sv = 0;
            float4 wv = make_float4(0.f, 0.f, 0.f, 0.f);
            if (e < s1) {
                sv = g_psrc[e];
                float4 raw = raw_score(ve, sv, e, sd);
                wv.x = __expf(raw.x - m.x) * rinv.x;
                wv.y = __expf(raw.y - m.y) * rinv.y;
                wv.z = __expf(raw.z - m.z) * rinv.z;
                wv.w = __expf(raw.w - m.w) * rinv.w;
            }
            int c2 = s1 - base; if (c2 > 32) c2 = 32;
            for (int j = 0; j < c2; j++) {
                int sj = __shfl_sync(0xffffffffu, sv, j);
                float wsel = head_w(wv, j, lane);
                float4 xr = *(const float4*)(xw + (size_t)sj * HC + lane * 4);
                acc.x += wsel * xr.x;
                acc.y += wsel * xr.y;
                acc.z += wsel * xr.z;
                acc.w += wsel * xr.w;
            }
        }
    }
    float4 b4 = *(const float4*)(bias + lane * 4);
    float4 o4;
    o4.x = fmaxf(acc.x + b4.x, 0.f);
    o4.y = fmaxf(acc.y + b4.y, 0.f);
    o4.z = fmaxf(acc.z + b4.z, 0.f);
    o4.w = fmaxf(acc.w + b4.w, 0.f);
    *(float4*)(hout + (size_t)n * HC + lane * 4) = o4;
}

// ---------------- output head ----------------
__global__ void __launch_bounds__(128) k_pool(const float* __restrict__ h,
                                              const int* __restrict__ batch) {
    int t = threadIdx.x;
    int n0 = blockIdx.x * 64;
    int nend = n0 + 64; if (nend > Nn) nend = Nn;
    float acc = 0.f;
    int cnt = 0;
    int curb = batch[n0];
    for (int n = n0; n < nend; n++) {
        int b = batch[n];
        if (b != curb) {
            atomicAdd(&g_gsum[curb * HC + t], acc);
            if (t == 0) atomicAdd(&g_gcnt[curb], cnt);
            curb = b; acc = 0.f; cnt = 0;
        }
        acc += h[(size_t)n * HC + t];
        cnt++;
    }
    atomicAdd(&g_gsum[curb * HC + t], acc);
    if (t == 0) atomicAdd(&g_gcnt[curb], cnt);
}

__global__ void k_head(const float* __restrict__ Wl, const float* __restrict__ bl,
                       float* __restrict__ out) {
    int tid = threadIdx.x;
    if (tid >= Bb * Aa) return;
    int b = tid >> 3, a = tid & 7;
    float ic = 1.0f / fmaxf((float)g_gcnt[b], 1.0f);
    float s = 0.f;
    for (int c = 0; c < HC; c++) s += g_gsum[b * HC + c] * Wl[c * Aa + a];
    out[tid] = tanhf(s * ic + bl[a]);
}

// ---------------- launch ----------------
extern "C" void kernel_launch(void* const* d_in, const int* in_sizes, int n_in,
                              void* d_out, int out_size) {
    const float* slots[22];
    int k = 0;
    const int* ei = nullptr;
    const int* batch = nullptr;
    for (int i = 0; i < n_in; i++) {
        int sz = in_sizes[i];
        if (sz == 2 * Ee) ei = (const int*)d_in[i];
        else if (sz == Nn) batch = (const int*)d_in[i];
        else if (k < 22) slots[k++] = (const float*)d_in[i];
    }
    const float* x      = slots[0];
    const float* eattr  = slots[1];
    const float* W[3]   = { slots[2],  slots[8],  slots[14] };
    const float* We[3]  = { slots[3],  slots[9],  slots[15] };
    const float* aS[3]  = { slots[4],  slots[10], slots[16] };
    const float* aD[3]  = { slots[5],  slots[11], slots[17] };
    const float* aE[3]  = { slots[6],  slots[12], slots[18] };
    const float* bia[3] = { slots[7],  slots[13], slots[19] };
    const float* Wl = slots[20];
    const float* bl = slots[21];
    float* out = (float*)d_out;

    float *p_xw, *p_hA, *p_hB;
    cudaGetSymbolAddress((void**)&p_xw, g_xw);
    cudaGetSymbolAddress((void**)&p_hA, g_hA);
    cudaGetSymbolAddress((void**)&p_hB, g_hB);

    k_init<<<(Nn + 255) / 256, 256>>>();
    k_count<<<(Ee + 255) / 256, 256>>>(ei);
    k_scan1<<<NB_SCAN, 256>>>();
    // launch #4 -> profiled by the fixed ncu window; verify the LDS fix here
    k_gemm<64><<<(Nn + 31) / 32, 128>>>(x, W[0], aS[0], aD[0], p_xw);
    k_scan2<<<1, 256>>>();
    k_scan3<<<NB_SCAN, 256>>>();
    k_scatter<<<(Ee + 255) / 256, 256>>>(ei, eattr);
    k_meanattr<<<(Nn * 32 + 255) / 256, 256>>>();

    const float* hin = x;
    float* houts[3] = { p_hA, p_hB, p_hA };
    for (int l = 0; l < 3; l++) {
        if (l > 0) k_gemm<128><<<(Nn + 31) / 32, 128>>>(hin, W[l], aS[l], aD[l], p_xw);
        k_agg<<<(Nn + 7) / 8, 256>>>(p_xw, We[l], aE[l], bia[l], houts[l]);
        hin = houts[l];
    }

    k_pool<<<(Nn + 63) / 64, 128>>>(hin, batch);
    k_head<<<1, 512>>>(Wl, bl, out);
}

// round 6
// speedup vs baseline: 1.4557x; 1.4557x over previous
#include <cuda_runtime.h>
#include <cfloat>
#include <math.h>

#define Nn 50000
#define Ee 800000
#define EF 850000     // Ee + Nn self loops
#define FIN 64
#define EDIM 16
#define Hh 4
#define Cc 32
#define HC 128
#define Bb 64
#define Aa 8
#define NB_SCAN ((Nn + 255) / 256)   // 196

// ---------------- scratch ----------------
__device__ float g_xw[Nn * HC];
__device__ float g_hA[Nn * HC];
__device__ float g_hB[Nn * HC];
__device__ int   g_cnt[Nn];
__device__ int   g_fill[Nn];
__device__ int   g_rowptr[Nn + 1];
__device__ int   g_bsum[256];
__device__ int   g_boff[256];
__device__ int   g_psrc[EF];
__device__ float g_pattr[(size_t)EF * EDIM];   // CSR-permuted edge attrs (+ self-loop mean rows)
__device__ float g_sce[EF * Hh];
__device__ float g_scs[Nn * Hh];
__device__ float g_scd[Nn * Hh];
__device__ float g_gsum[Bb * HC];
__device__ int   g_gcnt[Bb];

// ---------------- helpers ----------------
__device__ __forceinline__ float lrelu(float v) { return v > 0.f ? v : 0.2f * v; }

__device__ __forceinline__ float4 wmax4(float4 v) {
#pragma unroll
    for (int o = 16; o; o >>= 1) {
        v.x = fmaxf(v.x, __shfl_xor_sync(0xffffffffu, v.x, o));
        v.y = fmaxf(v.y, __shfl_xor_sync(0xffffffffu, v.y, o));
        v.z = fmaxf(v.z, __shfl_xor_sync(0xffffffffu, v.z, o));
        v.w = fmaxf(v.w, __shfl_xor_sync(0xffffffffu, v.w, o));
    }
    return v;
}
__device__ __forceinline__ float4 wsum4(float4 v) {
#pragma unroll
    for (int o = 16; o; o >>= 1) {
        v.x += __shfl_xor_sync(0xffffffffu, v.x, o);
        v.y += __shfl_xor_sync(0xffffffffu, v.y, o);
        v.z += __shfl_xor_sync(0xffffffffu, v.z, o);
        v.w += __shfl_xor_sync(0xffffffffu, v.w, o);
    }
    return v;
}

__device__ __forceinline__ float4 raw_score(int src, int e, float4 sd) {
    float4 ss = *(const float4*)(g_scs + src * 4);
    float4 se = *(const float4*)(g_sce + (size_t)e * 4);
    float4 r;
    r.x = lrelu(ss.x + sd.x + se.x);
    r.y = lrelu(ss.y + sd.y + se.y);
    r.z = lrelu(ss.z + sd.z + se.z);
    r.w = lrelu(ss.w + sd.w + se.w);
    return r;
}

// ---------------- preprocessing ----------------
__global__ void k_init() {
    int i = blockIdx.x * blockDim.x + threadIdx.x;
    if (i < Nn) { g_cnt[i] = 0; g_fill[i] = 0; }
    if (i < Bb * HC) g_gsum[i] = 0.f;
    if (i < Bb) g_gcnt[i] = 0;
}

__global__ void k_count(const int* __restrict__ ei) {
    int e = blockIdx.x * blockDim.x + threadIdx.x;
    if (e >= Ee) return;
    atomicAdd(&g_cnt[ei[Ee + e]], 1);
}

__global__ void k_scan1() {
    __shared__ int sh[256];
    int t = threadIdx.x;
    int i = blockIdx.x * 256 + t;
    int v = (i < Nn) ? (g_cnt[i] + 1) : 0;
    sh[t] = v;
    __syncthreads();
#pragma unroll
    for (int o = 1; o < 256; o <<= 1) {
        int u = (t >= o) ? sh[t - o] : 0;
        __syncthreads();
        sh[t] += u;
        __syncthreads();
    }
    if (i < Nn) g_rowptr[i] = sh[t] - v;
    if (t == 255) g_bsum[blockIdx.x] = sh[255];
}

__global__ void k_scan2() {
    __shared__ int sh[256];
    int t = threadIdx.x;
    int v = (t < NB_SCAN) ? g_bsum[t] : 0;
    sh[t] = v;
    __syncthreads();
#pragma unroll
    for (int o = 1; o < 256; o <<= 1) {
        int u = (t >= o) ? sh[t - o] : 0;
        __syncthreads();
        sh[t] += u;
        __syncthreads();
    }
    if (t < NB_SCAN) g_boff[t] = sh[t] - v;
    if (t == 255) g_rowptr[Nn] = sh[255];
}

__global__ void k_scan3() {
    int i = blockIdx.x * 256 + threadIdx.x;
    if (i < Nn) g_rowptr[i] += g_boff[blockIdx.x];
}

// scatter psrc + permute edge_attr into CSR order
__global__ void k_scatter(const int* __restrict__ ei, const float* __restrict__ eattr) {
    int e = blockIdx.x * blockDim.x + threadIdx.x;
    if (e >= Ee) return;
    int s = ei[e], d = ei[Ee + e];
    int pos = g_rowptr[d] + atomicAdd(&g_fill[d], 1);
    g_psrc[pos] = s;
    const float4* sp = (const float4*)(eattr + (size_t)e * EDIM);
    float4* dp = (float4*)(g_pattr + (size_t)pos * EDIM);
    dp[0] = sp[0]; dp[1] = sp[1]; dp[2] = sp[2]; dp[3] = sp[3];
}

// per-node mean of real in-edge attrs -> self-loop slot; psrc self = n
__global__ void __launch_bounds__(256) k_meanattr() {
    int n = (blockIdx.x * 256 + threadIdx.x) >> 5;
    int lane = threadIdx.x & 31;
    if (n >= Nn) return;
    int s0 = g_rowptr[n], s1 = g_rowptr[n + 1] - 1;   // real edges [s0,s1)
    float4 acc = make_float4(0.f, 0.f, 0.f, 0.f);
    const float4* pa = (const float4*)g_pattr;
    for (int r = s0 + (lane >> 2); r < s1; r += 8) {
        float4 v = pa[(size_t)r * 4 + (lane & 3)];
        acc.x += v.x; acc.y += v.y; acc.z += v.z; acc.w += v.w;
    }
#pragma unroll
    for (int o = 4; o < 32; o <<= 1) {
        acc.x += __shfl_xor_sync(0xffffffffu, acc.x, o);
        acc.y += __shfl_xor_sync(0xffffffffu, acc.y, o);
        acc.z += __shfl_xor_sync(0xffffffffu, acc.z, o);
        acc.w += __shfl_xor_sync(0xffffffffu, acc.w, o);
    }
    if (lane < 4) {
        float ic = 1.0f / fmaxf((float)(s1 - s0), 1.0f);
        acc.x *= ic; acc.y *= ic; acc.z *= ic; acc.w *= ic;
        ((float4*)g_pattr)[(size_t)s1 * 4 + lane] = acc;
    }
    if (lane == 0) g_psrc[s1] = n;
}

// ---------------- per-layer ----------------
// GEMM + fused per-row attention score epilogue.
// Lane owns 4 consecutive output columns (4*tx..4*tx+3): Ws read is 1 LDS.128
// per k-step, Out store is 1 STG.128 per row. k-tile = 32 -> 20KB smem -> high occ.
template <int K>
__global__ void __launch_bounds__(128) k_gemm(const float* __restrict__ A,
                                              const float* __restrict__ W,
                                              const float* __restrict__ a_s,
                                              const float* __restrict__ a_d,
                                              float* __restrict__ Out) {
    __shared__ float Ws[32][128];   // 16 KB
    __shared__ float Xs[32][32];    // 4 KB
    int tid = threadIdx.x;
    int tx = tid & 31, ty = tid >> 5;
    int rowbase = blockIdx.x * 32;
    float4 acc[8];
#pragma unroll
    for (int r = 0; r < 8; r++) acc[r] = make_float4(0.f, 0.f, 0.f, 0.f);

    for (int kc = 0; kc < K; kc += 32) {
        // load Ws: 32 rows x 128 cols = 1024 float4, 8 per thread
#pragma unroll
        for (int q = 0; q < 8; q++) {
            int idx = tid + 128 * q;
            int r = idx >> 5, c4 = idx & 31;
            *(float4*)&Ws[r][c4 * 4] = *(const float4*)&W[(size_t)(kc + r) * HC + c4 * 4];
        }
        // load Xs: 32 rows x 32 cols = 256 float4, 2 per thread
#pragma unroll
        for (int q = 0; q < 2; q++) {
            int idx = tid + 128 * q;
            int r = idx >> 3, c4 = idx & 7;
            int row = rowbase + r;
            float4 v = make_float4(0.f, 0.f, 0.f, 0.f);
            if (row < Nn) v = *(const float4*)&A[(size_t)row * K + kc + c4 * 4];
            *(float4*)&Xs[r][c4 * 4] = v;
        }
        __syncthreads();
#pragma unroll
        for (int k4 = 0; k4 < 32; k4 += 4) {
            float4 a4[8];
#pragma unroll
            for (int r = 0; r < 8; r++) a4[r] = *(const float4*)&Xs[ty + 4 * r][k4];
#pragma unroll
            for (int kk = 0; kk < 4; kk++) {
                float4 b4 = *(const float4*)&Ws[k4 + kk][tx * 4];
#pragma unroll
                for (int r = 0; r < 8; r++) {
                    float a = (kk == 0) ? a4[r].x : (kk == 1) ? a4[r].y : (kk == 2) ? a4[r].z : a4[r].w;
                    acc[r].x += a * b4.x;
                    acc[r].y += a * b4.y;
                    acc[r].z += a * b4.z;
                    acc[r].w += a * b4.w;
                }
            }
        }
        __syncthreads();
    }

    // per-lane attention slices: columns 4*tx..4*tx+3, head = tx>>3
    float4 as4 = *(const float4*)&a_s[tx * 4];
    float4 ad4 = *(const float4*)&a_d[tx * 4];
    int head = tx >> 3;

#pragma unroll
    for (int r = 0; r < 8; r++) {
        int row = rowbase + ty + 4 * r;
        if (row < Nn) {
            *(float4*)&Out[(size_t)row * HC + tx * 4] = acc[r];
            float ps = acc[r].x * as4.x + acc[r].y * as4.y + acc[r].z * as4.z + acc[r].w * as4.w;
            float pd = acc[r].x * ad4.x + acc[r].y * ad4.y + acc[r].z * ad4.z + acc[r].w * ad4.w;
#pragma unroll
            for (int o = 1; o < 8; o <<= 1) {
                ps += __shfl_xor_sync(0xffffffffu, ps, o);
                pd += __shfl_xor_sync(0xffffffffu, pd, o);
            }
            if ((tx & 7) == 0) {
                g_scs[row * 4 + head] = ps;
                g_scd[row * 4 + head] = pd;
            }
        }
    }
}

// sce over ALL EF slots (coalesced pattr read); Ve computed in-block
__global__ void k_sce(const float* __restrict__ We, const float* __restrict__ ae) {
    __shared__ float ve[EDIM * Hh];
    int t = threadIdx.x;
    if (t < EDIM * Hh) {
        int d = t >> 2, h = t & 3;
        float s = 0.f;
#pragma unroll
        for (int c = 0; c < Cc; c++) s += We[d * HC + h * Cc + c] * ae[h * Cc + c];
        ve[t] = s;
    }
    __syncthreads();
    int i = blockIdx.x * blockDim.x + threadIdx.x;
    if (i >= EF) return;
    const float* ap = g_pattr + (size_t)i * EDIM;
    float h0 = 0.f, h1 = 0.f, h2 = 0.f, h3 = 0.f;
#pragma unroll
    for (int q = 0; q < 4; q++) {
        float4 av = *(const float4*)(ap + q * 4);
        int d = q * 4;
        h0 += av.x * ve[d * 4 + 0] + av.y * ve[(d + 1) * 4 + 0] + av.z * ve[(d + 2) * 4 + 0] + av.w * ve[(d + 3) * 4 + 0];
        h1 += av.x * ve[d * 4 + 1] + av.y * ve[(d + 1) * 4 + 1] + av.z * ve[(d + 2) * 4 + 1] + av.w * ve[(d + 3) * 4 + 1];
        h2 += av.x * ve[d * 4 + 2] + av.y * ve[(d + 1) * 4 + 2] + av.z * ve[(d + 2) * 4 + 2] + av.w * ve[(d + 3) * 4 + 2];
        h3 += av.x * ve[d * 4 + 3] + av.y * ve[(d + 1) * 4 + 3] + av.z * ve[(d + 2) * 4 + 3] + av.w * ve[(d + 3) * 4 + 3];
    }
    *(float4*)(g_sce + (size_t)i * 4) = make_float4(h0, h1, h2, h3);
}

// pick this lane's head weight from edge j's float4 weights
__device__ __forceinline__ float head_w(float4 wv, int j, int lane) {
    float wx = __shfl_sync(0xffffffffu, wv.x, j);
    float wy = __shfl_sync(0xffffffffu, wv.y, j);
    float wz = __shfl_sync(0xffffffffu, wv.z, j);
    float ww = __shfl_sync(0xffffffffu, wv.w, j);
    return lane < 16 ? (lane < 8 ? wx : wy) : (lane < 24 ? wz : ww);
}

__global__ void __launch_bounds__(256) k_agg(const float* __restrict__ xw,
                                             const float* __restrict__ bias,
                                             float* __restrict__ hout) {
    int n = (blockIdx.x * 256 + threadIdx.x) >> 5;
    int lane = threadIdx.x & 31;
    if (n >= Nn) return;
    int s0 = g_rowptr[n], s1 = g_rowptr[n + 1];
    int deg = s1 - s0;
    float4 sd = *(const float4*)(g_scd + n * 4);
    float4 acc = make_float4(0.f, 0.f, 0.f, 0.f);

    if (deg <= 32) {
        int e = s0 + lane;
        bool v = e < s1;
        int srcv = 0;
        float4 raw = make_float4(-FLT_MAX, -FLT_MAX, -FLT_MAX, -FLT_MAX);
        if (v) {
            srcv = g_psrc[e];
            raw = raw_score(srcv, e, sd);
        }
        float4 m = wmax4(raw);
        float4 a = make_float4(0.f, 0.f, 0.f, 0.f);
        if (v) {
            a.x = __expf(raw.x - m.x);
            a.y = __expf(raw.y - m.y);
            a.z = __expf(raw.z - m.z);
            a.w = __expf(raw.w - m.w);
        }
        float4 s = wsum4(a);
        float4 w;
        w.x = a.x / (s.x + 1e-16f);
        w.y = a.y / (s.y + 1e-16f);
        w.z = a.z / (s.z + 1e-16f);
        w.w = a.w / (s.w + 1e-16f);
        for (int j = 0; j < deg; j++) {
            int sj = __shfl_sync(0xffffffffu, srcv, j);
            float wsel = head_w(w, j, lane);
            float4 xr = *(const float4*)(xw + (size_t)sj * HC + lane * 4);
            acc.x += wsel * xr.x;
            acc.y += wsel * xr.y;
            acc.z += wsel * xr.z;
            acc.w += wsel * xr.w;
        }
    } else {
        float4 pm = make_float4(-FLT_MAX, -FLT_MAX, -FLT_MAX, -FLT_MAX);
        for (int base = s0; base < s1; base += 32) {
            int e = base + lane;
            if (e < s1) {
                float4 raw = raw_score(g_psrc[e], e, sd);
                pm.x = fmaxf(pm.x, raw.x); pm.y = fmaxf(pm.y, raw.y);
                pm.z = fmaxf(pm.z, raw.z); pm.w = fmaxf(pm.w, raw.w);
            }
        }
        float4 m = wmax4(pm);
        float4 ps = make_float4(0.f, 0.f, 0.f, 0.f);
        for (int base = s0; base < s1; base += 32) {
            int e = base + lane;
            if (e < s1) {
                float4 raw = raw_score(g_psrc[e], e, sd);
                ps.x += __expf(raw.x - m.x);
                ps.y += __expf(raw.y - m.y);
                ps.z += __expf(raw.z - m.z);
                ps.w += __expf(raw.w - m.w);
            }
        }
        float4 s = wsum4(ps);
        float4 rinv;
        rinv.x = 1.f / (s.x + 1e-16f);
        rinv.y = 1.f / (s.y + 1e-16f);
        rinv.z = 1.f / (s.z + 1e-16f);
        rinv.w = 1.f / (s.w + 1e-16f);
        for (int base = s0; base < s1; base += 32) {
            int e = base + lane;
            int sv = 0;
            float4 wv = make_float4(0.f, 0.f, 0.f, 0.f);
            if (e < s1) {
                sv = g_psrc[e];
                float4 raw = raw_score(sv, e, sd);
                wv.x = __expf(raw.x - m.x) * rinv.x;
                wv.y = __expf(raw.y - m.y) * rinv.y;
                wv.z = __expf(raw.z - m.z) * rinv.z;
                wv.w = __expf(raw.w - m.w) * rinv.w;
            }
            int c2 = s1 - base; if (c2 > 32) c2 = 32;
            for (int j = 0; j < c2; j++) {
                int sj = __shfl_sync(0xffffffffu, sv, j);
                float wsel = head_w(wv, j, lane);
                float4 xr = *(const float4*)(xw + (size_t)sj * HC + lane * 4);
                acc.x += wsel * xr.x;
                acc.y += wsel * xr.y;
                acc.z += wsel * xr.z;
                acc.w += wsel * xr.w;
            }
        }
    }
    float4 b4 = *(const float4*)(bias + lane * 4);
    float4 o4;
    o4.x = fmaxf(acc.x + b4.x, 0.f);
    o4.y = fmaxf(acc.y + b4.y, 0.f);
    o4.z = fmaxf(acc.z + b4.z, 0.f);
    o4.w = fmaxf(acc.w + b4.w, 0.f);
    *(float4*)(hout + (size_t)n * HC + lane * 4) = o4;
}

// ---------------- output head ----------------
__global__ void __launch_bounds__(128) k_pool(const float* __restrict__ h,
                                              const int* __restrict__ batch) {
    int t = threadIdx.x;
    int n0 = blockIdx.x * 64;
    int nend = n0 + 64; if (nend > Nn) nend = Nn;
    float acc = 0.f;
    int cnt = 0;
    int curb = batch[n0];
    for (int n = n0; n < nend; n++) {
        int b = batch[n];
        if (b != curb) {
            atomicAdd(&g_gsum[curb * HC + t], acc);
            if (t == 0) atomicAdd(&g_gcnt[curb], cnt);
            curb = b; acc = 0.f; cnt = 0;
        }
        acc += h[(size_t)n * HC + t];
        cnt++;
    }
    atomicAdd(&g_gsum[curb * HC + t], acc);
    if (t == 0) atomicAdd(&g_gcnt[curb], cnt);
}

__global__ void k_head(const float* __restrict__ Wl, const float* __restrict__ bl,
                       float* __restrict__ out) {
    int tid = threadIdx.x;
    if (tid >= Bb * Aa) return;
    int b = tid >> 3, a = tid & 7;
    float ic = 1.0f / fmaxf((float)g_gcnt[b], 1.0f);
    float s = 0.f;
    for (int c = 0; c < HC; c++) s += g_gsum[b * HC + c] * Wl[c * Aa + a];
    out[tid] = tanhf(s * ic + bl[a]);
}

// ---------------- launch ----------------
extern "C" void kernel_launch(void* const* d_in, const int* in_sizes, int n_in,
                              void* d_out, int out_size) {
    const float* slots[22];
    int k = 0;
    const int* ei = nullptr;
    const int* batch = nullptr;
    for (int i = 0; i < n_in; i++) {
        int sz = in_sizes[i];
        if (sz == 2 * Ee) ei = (const int*)d_in[i];
        else if (sz == Nn) batch = (const int*)d_in[i];
        else if (k < 22) slots[k++] = (const float*)d_in[i];
    }
    const float* x      = slots[0];
    const float* eattr  = slots[1];
    const float* W[3]   = { slots[2],  slots[8],  slots[14] };
    const float* We[3]  = { slots[3],  slots[9],  slots[15] };
    const float* aS[3]  = { slots[4],  slots[10], slots[16] };
    const float* aD[3]  = { slots[5],  slots[11], slots[17] };
    const float* aE[3]  = { slots[6],  slots[12], slots[18] };
    const float* bia[3] = { slots[7],  slots[13], slots[19] };
    const float* Wl = slots[20];
    const float* bl = slots[21];
    float* out = (float*)d_out;

    float *p_xw, *p_hA, *p_hB;
    cudaGetSymbolAddress((void**)&p_xw, g_xw);
    cudaGetSymbolAddress((void**)&p_hA, g_hA);
    cudaGetSymbolAddress((void**)&p_hB, g_hB);

    k_init<<<(Nn + 255) / 256, 256>>>();
    k_count<<<(Ee + 255) / 256, 256>>>(ei);
    k_scan1<<<NB_SCAN, 256>>>();
    // launch #4 -> profiled by the fixed ncu window; verify the LDS.128/occupancy fix
    k_gemm<64><<<(Nn + 31) / 32, 128>>>(x, W[0], aS[0], aD[0], p_xw);
    k_scan2<<<1, 256>>>();
    k_scan3<<<NB_SCAN, 256>>>();
    k_scatter<<<(Ee + 255) / 256, 256>>>(ei, eattr);
    k_meanattr<<<(Nn * 32 + 255) / 256, 256>>>();

    const float* hin = x;
    float* houts[3] = { p_hA, p_hB, p_hA };
    for (int l = 0; l < 3; l++) {
        if (l > 0) k_gemm<128><<<(Nn + 31) / 32, 128>>>(hin, W[l], aS[l], aD[l], p_xw);
        k_sce<<<(EF + 255) / 256, 256>>>(We[l], aE[l]);
        k_agg<<<(Nn + 7) / 8, 256>>>(p_xw, bia[l], houts[l]);
        hin = houts[l];
    }

    k_pool<<<(Nn + 63) / 64, 128>>>(hin, batch);
    k_head<<<1, 512>>>(Wl, bl, out);
}

// round 8
// speedup vs baseline: 1.5142x; 1.0402x over previous
#include <cuda_runtime.h>
#include <cfloat>
#include <math.h>

#define Nn 50000
#define Ee 800000
#define EF 850000     // Ee + Nn self loops
#define FIN 64
#define EDIM 16
#define Hh 4
#define Cc 32
#define HC 128
#define Bb 64
#define Aa 8
#define NB_SCAN ((Nn + 255) / 256)   // 196

// ---------------- scratch ----------------
__device__ float g_xw[Nn * HC];
__device__ float g_hA[Nn * HC];
__device__ float g_hB[Nn * HC];
__device__ int   g_cnt[Nn];
__device__ int   g_fill[Nn];
__device__ int   g_rowptr[Nn + 1];
__device__ int   g_bsum[256];
__device__ int   g_boff[256];
__device__ int   g_psrc[EF];
__device__ float g_pattr[(size_t)EF * EDIM];   // CSR-permuted edge attrs (+ self-loop mean rows)
__device__ float g_sce[EF * Hh];
__device__ float g_scs[Nn * Hh];
__device__ float g_scd[Nn * Hh];
__device__ float g_gsum[Bb * HC];
__device__ int   g_gcnt[Bb];

// ---------------- helpers ----------------
__device__ __forceinline__ float lrelu(float v) { return v > 0.f ? v : 0.2f * v; }

__device__ __forceinline__ float4 wmax4(float4 v) {
#pragma unroll
    for (int o = 16; o; o >>= 1) {
        v.x = fmaxf(v.x, __shfl_xor_sync(0xffffffffu, v.x, o));
        v.y = fmaxf(v.y, __shfl_xor_sync(0xffffffffu, v.y, o));
        v.z = fmaxf(v.z, __shfl_xor_sync(0xffffffffu, v.z, o));
        v.w = fmaxf(v.w, __shfl_xor_sync(0xffffffffu, v.w, o));
    }
    return v;
}
__device__ __forceinline__ float4 wsum4(float4 v) {
#pragma unroll
    for (int o = 16; o; o >>= 1) {
        v.x += __shfl_xor_sync(0xffffffffu, v.x, o);
        v.y += __shfl_xor_sync(0xffffffffu, v.y, o);
        v.z += __shfl_xor_sync(0xffffffffu, v.z, o);
        v.w += __shfl_xor_sync(0xffffffffu, v.w, o);
    }
    return v;
}

__device__ __forceinline__ float4 raw_score(int src, int e, float4 sd) {
    float4 ss = *(const float4*)(g_scs + src * 4);
    float4 se = *(const float4*)(g_sce + (size_t)e * 4);
    float4 r;
    r.x = lrelu(ss.x + sd.x + se.x);
    r.y = lrelu(ss.y + sd.y + se.y);
    r.z = lrelu(ss.z + sd.z + se.z);
    r.w = lrelu(ss.w + sd.w + se.w);
    return r;
}

// ---------------- preprocessing ----------------
__global__ void k_init() {
    int i = blockIdx.x * blockDim.x + threadIdx.x;
    if (i < Nn) { g_cnt[i] = 0; g_fill[i] = 0; }
    if (i < Bb * HC) g_gsum[i] = 0.f;
    if (i < Bb) g_gcnt[i] = 0;
}

__global__ void k_count(const int* __restrict__ ei) {
    int e = blockIdx.x * blockDim.x + threadIdx.x;
    if (e >= Ee) return;
    atomicAdd(&g_cnt[ei[Ee + e]], 1);
}

__global__ void k_scan1() {
    __shared__ int sh[256];
    int t = threadIdx.x;
    int i = blockIdx.x * 256 + t;
    int v = (i < Nn) ? (g_cnt[i] + 1) : 0;
    sh[t] = v;
    __syncthreads();
#pragma unroll
    for (int o = 1; o < 256; o <<= 1) {
        int u = (t >= o) ? sh[t - o] : 0;
        __syncthreads();
        sh[t] += u;
        __syncthreads();
    }
    if (i < Nn) g_rowptr[i] = sh[t] - v;
    if (t == 255) g_bsum[blockIdx.x] = sh[255];
}

__global__ void k_scan2() {
    __shared__ int sh[256];
    int t = threadIdx.x;
    int v = (t < NB_SCAN) ? g_bsum[t] : 0;
    sh[t] = v;
    __syncthreads();
#pragma unroll
    for (int o = 1; o < 256; o <<= 1) {
        int u = (t >= o) ? sh[t - o] : 0;
        __syncthreads();
        sh[t] += u;
        __syncthreads();
    }
    if (t < NB_SCAN) g_boff[t] = sh[t] - v;
    if (t == 255) g_rowptr[Nn] = sh[255];
}

__global__ void k_scan3() {
    int i = blockIdx.x * 256 + threadIdx.x;
    if (i < Nn) g_rowptr[i] += g_boff[blockIdx.x];
}

// scatter psrc + permute edge_attr into CSR order
__global__ void k_scatter(const int* __restrict__ ei, const float* __restrict__ eattr) {
    int e = blockIdx.x * blockDim.x + threadIdx.x;
    if (e >= Ee) return;
    int s = ei[e], d = ei[Ee + e];
    int pos = g_rowptr[d] + atomicAdd(&g_fill[d], 1);
    g_psrc[pos] = s;
    const float4* sp = (const float4*)(eattr + (size_t)e * EDIM);
    float4* dp = (float4*)(g_pattr + (size_t)pos * EDIM);
    dp[0] = sp[0]; dp[1] = sp[1]; dp[2] = sp[2]; dp[3] = sp[3];
}

// per-node mean of real in-edge attrs -> self-loop slot; psrc self = n
__global__ void __launch_bounds__(256) k_meanattr() {
    int n = (blockIdx.x * 256 + threadIdx.x) >> 5;
    int lane = threadIdx.x & 31;
    if (n >= Nn) return;
    int s0 = g_rowptr[n], s1 = g_rowptr[n + 1] - 1;   // real edges [s0,s1)
    float4 acc = make_float4(0.f, 0.f, 0.f, 0.f);
    const float4* pa = (const float4*)g_pattr;
    for (int r = s0 + (lane >> 2); r < s1; r += 8) {
        float4 v = pa[(size_t)r * 4 + (lane & 3)];
        acc.x += v.x; acc.y += v.y; acc.z += v.z; acc.w += v.w;
    }
#pragma unroll
    for (int o = 4; o < 32; o <<= 1) {
        acc.x += __shfl_xor_sync(0xffffffffu, acc.x, o);
        acc.y += __shfl_xor_sync(0xffffffffu, acc.y, o);
        acc.z += __shfl_xor_sync(0xffffffffu, acc.z, o);
        acc.w += __shfl_xor_sync(0xffffffffu, acc.w, o);
    }
    if (lane < 4) {
        float ic = 1.0f / fmaxf((float)(s1 - s0), 1.0f);
        acc.x *= ic; acc.y *= ic; acc.z *= ic; acc.w *= ic;
        ((float4*)g_pattr)[(size_t)s1 * 4 + lane] = acc;
    }
    if (lane == 0) g_psrc[s1] = n;
}

// ---------------- per-layer ----------------
// GEMM + fused per-row attention score epilogue.
template <int K>
__global__ void __launch_bounds__(128, 6) k_gemm(const float* __restrict__ A,
                                                 const float* __restrict__ W,
                                                 const float* __restrict__ a_s,
                                                 const float* __restrict__ a_d,
                                                 float* __restrict__ Out) {
    __shared__ float Ws[32][128];   // 16 KB
    __shared__ float Xs[32][32];    // 4 KB
    int tid = threadIdx.x;
    int tx = tid & 31, ty = tid >> 5;
    int rowbase = blockIdx.x * 32;
    float4 acc[8];
#pragma unroll
    for (int r = 0; r < 8; r++) acc[r] = make_float4(0.f, 0.f, 0.f, 0.f);

    for (int kc = 0; kc < K; kc += 32) {
#pragma unroll
        for (int q = 0; q < 8; q++) {
            int idx = tid + 128 * q;
            int r = idx >> 5, c4 = idx & 31;
            *(float4*)&Ws[r][c4 * 4] = *(const float4*)&W[(size_t)(kc + r) * HC + c4 * 4];
        }
#pragma unroll
        for (int q = 0; q < 2; q++) {
            int idx = tid + 128 * q;
            int r = idx >> 3, c4 = idx & 7;
            int row = rowbase + r;
            float4 v = make_float4(0.f, 0.f, 0.f, 0.f);
            if (row < Nn) v = *(const float4*)&A[(size_t)row * K + kc + c4 * 4];
            *(float4*)&Xs[r][c4 * 4] = v;
        }
        __syncthreads();
#pragma unroll
        for (int k4 = 0; k4 < 32; k4 += 4) {
            float4 a4[8];
#pragma unroll
            for (int r = 0; r < 8; r++) a4[r] = *(const float4*)&Xs[ty + 4 * r][k4];
#pragma unroll
            for (int kk = 0; kk < 4; kk++) {
                float4 b4 = *(const float4*)&Ws[k4 + kk][tx * 4];
#pragma unroll
                for (int r = 0; r < 8; r++) {
                    float a = (kk == 0) ? a4[r].x : (kk == 1) ? a4[r].y : (kk == 2) ? a4[r].z : a4[r].w;
                    acc[r].x += a * b4.x;
                    acc[r].y += a * b4.y;
                    acc[r].z += a * b4.z;
                    acc[r].w += a * b4.w;
                }
            }
        }
        __syncthreads();
    }

    float4 as4 = *(const float4*)&a_s[tx * 4];
    float4 ad4 = *(const float4*)&a_d[tx * 4];
    int head = tx >> 3;

#pragma unroll
    for (int r = 0; r < 8; r++) {
        int row = rowbase + ty + 4 * r;
        if (row < Nn) {
            *(float4*)&Out[(size_t)row * HC + tx * 4] = acc[r];
            float ps = acc[r].x * as4.x + acc[r].y * as4.y + acc[r].z * as4.z + acc[r].w * as4.w;
            float pd = acc[r].x * ad4.x + acc[r].y * ad4.y + acc[r].z * ad4.z + acc[r].w * ad4.w;
#pragma unroll
            for (int o = 1; o < 8; o <<= 1) {
                ps += __shfl_xor_sync(0xffffffffu, ps, o);
                pd += __shfl_xor_sync(0xffffffffu, pd, o);
            }
            if ((tx & 7) == 0) {
                g_scs[row * 4 + head] = ps;
                g_scd[row * 4 + head] = pd;
            }
        }
    }
}

// sce over ALL EF slots (coalesced pattr read); Ve computed in-block
__global__ void k_sce(const float* __restrict__ We, const float* __restrict__ ae) {
    __shared__ float ve[EDIM * Hh];
    int t = threadIdx.x;
    if (t < EDIM * Hh) {
        int d = t >> 2, h = t & 3;
        float s = 0.f;
#pragma unroll
        for (int c = 0; c < Cc; c++) s += We[d * HC + h * Cc + c] * ae[h * Cc + c];
        ve[t] = s;
    }
    __syncthreads();
    int i = blockIdx.x * blockDim.x + threadIdx.x;
    if (i >= EF) return;
    const float* ap = g_pattr + (size_t)i * EDIM;
    float h0 = 0.f, h1 = 0.f, h2 = 0.f, h3 = 0.f;
#pragma unroll
    for (int q = 0; q < 4; q++) {
        float4 av = *(const float4*)(ap + q * 4);
        int d = q * 4;
        h0 += av.x * ve[d * 4 + 0] + av.y * ve[(d + 1) * 4 + 0] + av.z * ve[(d + 2) * 4 + 0] + av.w * ve[(d + 3) * 4 + 0];
        h1 += av.x * ve[d * 4 + 1] + av.y * ve[(d + 1) * 4 + 1] + av.z * ve[(d + 2) * 4 + 1] + av.w * ve[(d + 3) * 4 + 1];
        h2 += av.x * ve[d * 4 + 2] + av.y * ve[(d + 1) * 4 + 2] + av.z * ve[(d + 2) * 4 + 2] + av.w * ve[(d + 3) * 4 + 2];
        h3 += av.x * ve[d * 4 + 3] + av.y * ve[(d + 1) * 4 + 3] + av.z * ve[(d + 2) * 4 + 3] + av.w * ve[(d + 3) * 4 + 3];
    }
    *(float4*)(g_sce + (size_t)i * 4) = make_float4(h0, h1, h2, h3);
}

// pick this lane's head weight from edge j's float4 weights (deg>32 fallback)
__device__ __forceinline__ float head_w(float4 wv, int j, int lane) {
    float wx = __shfl_sync(0xffffffffu, wv.x, j);
    float wy = __shfl_sync(0xffffffffu, wv.y, j);
    float wz = __shfl_sync(0xffffffffu, wv.z, j);
    float ww = __shfl_sync(0xffffffffu, wv.w, j);
    return lane < 16 ? (lane < 8 ? wx : wy) : (lane < 24 ? wz : ww);
}

__global__ void __launch_bounds__(256) k_agg(const float* __restrict__ xw,
                                             const float* __restrict__ bias,
                                             float* __restrict__ hout) {
    __shared__ int   s_src[8][32];
    __shared__ float s_w[8][32][4];
    int wid = threadIdx.x >> 5;
    int n = (blockIdx.x * 256 + threadIdx.x) >> 5;
    int lane = threadIdx.x & 31;
    if (n >= Nn) return;
    int s0 = g_rowptr[n], s1 = g_rowptr[n + 1];
    int deg = s1 - s0;
    float4 sd = *(const float4*)(g_scd + n * 4);
    float4 acc = make_float4(0.f, 0.f, 0.f, 0.f);

    if (deg <= 32) {
        int e = s0 + lane;
        bool v = e < s1;
        int srcv = 0;
        float4 raw = make_float4(-FLT_MAX, -FLT_MAX, -FLT_MAX, -FLT_MAX);
        if (v) {
            srcv = g_psrc[e];
            raw = raw_score(srcv, e, sd);
        }
        float4 m = wmax4(raw);
        float4 a = make_float4(0.f, 0.f, 0.f, 0.f);
        if (v) {
            a.x = __expf(raw.x - m.x);
            a.y = __expf(raw.y - m.y);
            a.z = __expf(raw.z - m.z);
            a.w = __expf(raw.w - m.w);
        }
        float4 s = wsum4(a);
        // stage (src, w) in shared: gather loop reads 1 LDS each instead of shuffles
        s_src[wid][lane] = srcv;
        s_w[wid][lane][0] = a.x / (s.x + 1e-16f);
        s_w[wid][lane][1] = a.y / (s.y + 1e-16f);
        s_w[wid][lane][2] = a.z / (s.z + 1e-16f);
        s_w[wid][lane][3] = a.w / (s.w + 1e-16f);
        __syncwarp();

        int c = lane >> 3;
        int j = 0;
        for (; j + 4 <= deg; j += 4) {
            int sj0 = s_src[wid][j],     sj1 = s_src[wid][j + 1];
            int sj2 = s_src[wid][j + 2], sj3 = s_src[wid][j + 3];
            float w0 = s_w[wid][j][c],     w1 = s_w[wid][j + 1][c];
            float w2 = s_w[wid][j + 2][c], w3 = s_w[wid][j + 3][c];
            float4 x0 = *(const float4*)(xw + (size_t)sj0 * HC + lane * 4);
            float4 x1 = *(const float4*)(xw + (size_t)sj1 * HC + lane * 4);
            float4 x2 = *(const float4*)(xw + (size_t)sj2 * HC + lane * 4);
            float4 x3 = *(const float4*)(xw + (size_t)sj3 * HC + lane * 4);
            acc.x += w0 * x0.x + w1 * x1.x + w2 * x2.x + w3 * x3.x;
            acc.y += w0 * x0.y + w1 * x1.y + w2 * x2.y + w3 * x3.y;
            acc.z += w0 * x0.z + w1 * x1.z + w2 * x2.z + w3 * x3.z;
            acc.w += w0 * x0.w + w1 * x1.w + w2 * x2.w + w3 * x3.w;
        }
        for (; j < deg; j++) {
            int sj = s_src[wid][j];
            float wj = s_w[wid][j][c];
            float4 xr = *(const float4*)(xw + (size_t)sj * HC + lane * 4);
            acc.x += wj * xr.x;
            acc.y += wj * xr.y;
            acc.z += wj * xr.z;
            acc.w += wj * xr.w;
        }
    } else {
        float4 pm = make_float4(-FLT_MAX, -FLT_MAX, -FLT_MAX, -FLT_MAX);
        for (int base = s0; base < s1; base += 32) {
            int e = base + lane;
            if (e < s1) {
                float4 raw = raw_score(g_psrc[e], e, sd);
                pm.x = fmaxf(pm.x, raw.x); pm.y = fmaxf(pm.y, raw.y);
                pm.z = fmaxf(pm.z, raw.z); pm.w = fmaxf(pm.w, raw.w);
            }
        }
        float4 m = wmax4(pm);
        float4 ps = make_float4(0.f, 0.f, 0.f, 0.f);
        for (int base = s0; base < s1; base += 32) {
            int e = base + lane;
            if (e < s1) {
                float4 raw = raw_score(g_psrc[e], e, sd);
                ps.x += __expf(raw.x - m.x);
                ps.y += __expf(raw.y - m.y);
                ps.z += __expf(raw.z - m.z);
                ps.w += __expf(raw.w - m.w);
            }
        }
        float4 s = wsum4(ps);
        float4 rinv;
        rinv.x = 1.f / (s.x + 1e-16f);
        rinv.y = 1.f / (s.y + 1e-16f);
        rinv.z = 1.f / (s.z + 1e-16f);
        rinv.w = 1.f / (s.w + 1e-16f);
        for (int base = s0; base < s1; base += 32) {
            int e = base + lane;
            int sv = 0;
            float4 wv = make_float4(0.f, 0.f, 0.f, 0.f);
            if (e < s1) {
                sv = g_psrc[e];
                float4 raw = raw_score(sv, e, sd);
                wv.x = __expf(raw.x - m.x) * rinv.x;
                wv.y = __expf(raw.y - m.y) * rinv.y;
                wv.z = __expf(raw.z - m.z) * rinv.z;
                wv.w = __expf(raw.w - m.w) * rinv.w;
            }
            int c2 = s1 - base; if (c2 > 32) c2 = 32;
            for (int j = 0; j < c2; j++) {
                int sj = __shfl_sync(0xffffffffu, sv, j);
                float wsel = head_w(wv, j, lane);
                float4 xr = *(const float4*)(xw + (size_t)sj * HC + lane * 4);
                acc.x += wsel * xr.x;
                acc.y += wsel * xr.y;
                acc.z += wsel * xr.z;
                acc.w += wsel * xr.w;
            }
        }
    }
    float4 b4 = *(const float4*)(bias + lane * 4);
    float4 o4;
    o4.x = fmaxf(acc.x + b4.x, 0.f);
    o4.y = fmaxf(acc.y + b4.y, 0.f);
    o4.z = fmaxf(acc.z + b4.z, 0.f);
    o4.w = fmaxf(acc.w + b4.w, 0.f);
    *(float4*)(hout + (size_t)n * HC + lane * 4) = o4;
}

// ---------------- output head ----------------
__global__ void __launch_bounds__(128) k_pool(const float* __restrict__ h,
                                              const int* __restrict__ batch) {
    int t = threadIdx.x;
    int n0 = blockIdx.x * 64;
    int nend = n0 + 64; if (nend > Nn) nend = Nn;
    float acc = 0.f;
    int cnt = 0;
    int curb = batch[n0];
    for (int n = n0; n < nend; n++) {
        int b = batch[n];
        if (b != curb) {
            atomicAdd(&g_gsum[curb * HC + t], acc);
            if (t == 0) atomicAdd(&g_gcnt[curb], cnt);
            curb = b; acc = 0.f; cnt = 0;
        }
        acc += h[(size_t)n * HC + t];
        cnt++;
    }
    atomicAdd(&g_gsum[curb * HC + t], acc);
    if (t == 0) atomicAdd(&g_gcnt[curb], cnt);
}

__global__ void k_head(const float* __restrict__ Wl, const float* __restrict__ bl,
                       float* __restrict__ out) {
    int tid = threadIdx.x;
    if (tid >= Bb * Aa) return;
    int b = tid >> 3, a = tid & 7;
    float ic = 1.0f / fmaxf((float)g_gcnt[b], 1.0f);
    float s = 0.f;
    for (int c = 0; c < HC; c++) s += g_gsum[b * HC + c] * Wl[c * Aa + a];
    out[tid] = tanhf(s * ic + bl[a]);
}

// ---------------- launch ----------------
extern "C" void kernel_launch(void* const* d_in, const int* in_sizes, int n_in,
                              void* d_out, int out_size) {
    const float* slots[22];
    int k = 0;
    const int* ei = nullptr;
    const int* batch = nullptr;
    for (int i = 0; i < n_in; i++) {
        int sz = in_sizes[i];
        if (sz == 2 * Ee) ei = (const int*)d_in[i];
        else if (sz == Nn) batch = (const int*)d_in[i];
        else if (k < 22) slots[k++] = (const float*)d_in[i];
    }
    const float* x      = slots[0];
    const float* eattr  = slots[1];
    const float* W[3]   = { slots[2],  slots[8],  slots[14] };
    const float* We[3]  = { slots[3],  slots[9],  slots[15] };
    const float* aS[3]  = { slots[4],  slots[10], slots[16] };
    const float* aD[3]  = { slots[5],  slots[11], slots[17] };
    const float* aE[3]  = { slots[6],  slots[12], slots[18] };
    const float* bia[3] = { slots[7],  slots[13], slots[19] };
    const float* Wl = slots[20];
    const float* bl = slots[21];
    float* out = (float*)d_out;

    float *p_xw, *p_hA, *p_hB;
    cudaGetSymbolAddress((void**)&p_xw, g_xw);
    cudaGetSymbolAddress((void**)&p_hA, g_hA);
    cudaGetSymbolAddress((void**)&p_hB, g_hB);

    k_init<<<(Nn + 255) / 256, 256>>>();
    k_count<<<(Ee + 255) / 256, 256>>>(ei);
    k_scan1<<<NB_SCAN, 256>>>();
    // launch #4 -> profiled by the fixed ncu window; verify occupancy effect
    k_gemm<64><<<(Nn + 31) / 32, 128>>>(x, W[0], aS[0], aD[0], p_xw);
    k_scan2<<<1, 256>>>();
    k_scan3<<<NB_SCAN, 256>>>();
    k_scatter<<<(Ee + 255) / 256, 256>>>(ei, eattr);
    k_meanattr<<<(Nn * 32 + 255) / 256, 256>>>();

    const float* hin = x;
    float* houts[3] = { p_hA, p_hB, p_hA };
    for (int l = 0; l < 3; l++) {
        if (l > 0) k_gemm<128><<<(Nn + 31) / 32, 128>>>(hin, W[l], aS[l], aD[l], p_xw);
        k_sce<<<(EF + 255) / 256, 256>>>(We[l], aE[l]);
        k_agg<<<(Nn + 7) / 8, 256>>>(p_xw, bia[l], houts[l]);
        hin = houts[l];
    }

    k_pool<<<(Nn + 63) / 64, 128>>>(hin, batch);
    k_head<<<1, 512>>>(Wl, bl, out);
}

// round 11
// speedup vs baseline: 1.5975x; 1.0550x over previous
#include <cuda_runtime.h>
#include <cstdint>
#include <cfloat>
#include <math.h>

#define Nn 50000
#define Ee 800000
#define EF 850000     // Ee + Nn self loops
#define FIN 64
#define EDIM 16
#define Hh 4
#define Cc 32
#define HC 128
#define Bb 64
#define Aa 8
#define NB_SCAN ((Nn + 255) / 256)   // 196

// ---------------- scratch ----------------
__device__ float g_xw[Nn * HC];
__device__ float g_hA[Nn * HC];
__device__ float g_hB[Nn * HC];
__device__ int   g_cnt[Nn];
__device__ int   g_fill[Nn];
__device__ int   g_rowptr[Nn + 1];
__device__ int   g_bsum[256];
__device__ int   g_boff[256];
__device__ int   g_psrc[EF];
__device__ float g_pattr[(size_t)EF * EDIM];     // CSR-permuted edge attrs (+ self-loop mean rows)
__device__ float g_sce[(size_t)3 * EF * Hh];     // per-layer edge scores
__device__ float g_scs[Nn * Hh];
__device__ float g_scd[Nn * Hh];
__device__ float g_gsum[Bb * HC];
__device__ int   g_gcnt[Bb];

// ---------------- helpers ----------------
__device__ __forceinline__ float lrelu(float v) { return v > 0.f ? v : 0.2f * v; }

__device__ __forceinline__ void cpa16(unsigned int saddr, const void* g, int sz) {
    asm volatile("cp.async.cg.shared.global [%0], [%1], 16, %2;\n"
                 :: "r"(saddr), "l"(g), "r"(sz) : "memory");
}

__device__ __forceinline__ float4 wmax4(float4 v) {
#pragma unroll
    for (int o = 16; o; o >>= 1) {
        v.x = fmaxf(v.x, __shfl_xor_sync(0xffffffffu, v.x, o));
        v.y = fmaxf(v.y, __shfl_xor_sync(0xffffffffu, v.y, o));
        v.z = fmaxf(v.z, __shfl_xor_sync(0xffffffffu, v.z, o));
        v.w = fmaxf(v.w, __shfl_xor_sync(0xffffffffu, v.w, o));
    }
    return v;
}
__device__ __forceinline__ float4 wsum4(float4 v) {
#pragma unroll
    for (int o = 16; o; o >>= 1) {
        v.x += __shfl_xor_sync(0xffffffffu, v.x, o);
        v.y += __shfl_xor_sync(0xffffffffu, v.y, o);
        v.z += __shfl_xor_sync(0xffffffffu, v.z, o);
        v.w += __shfl_xor_sync(0xffffffffu, v.w, o);
    }
    return v;
}

__device__ __forceinline__ float4 raw_score(const float* __restrict__ sce,
                                            int src, int e, float4 sd) {
    float4 ss = *(const float4*)(g_scs + src * 4);
    float4 se = *(const float4*)(sce + (size_t)e * 4);
    float4 r;
    r.x = lrelu(ss.x + sd.x + se.x);
    r.y = lrelu(ss.y + sd.y + se.y);
    r.z = lrelu(ss.z + sd.z + se.z);
    r.w = lrelu(ss.w + sd.w + se.w);
    return r;
}

// ---------------- preprocessing ----------------
__global__ void k_init() {
    int i = blockIdx.x * blockDim.x + threadIdx.x;
    if (i < Nn) { g_cnt[i] = 0; g_fill[i] = 0; }
    if (i < Bb * HC) g_gsum[i] = 0.f;
    if (i < Bb) g_gcnt[i] = 0;
}

__global__ void k_count(const int* __restrict__ ei) {
    int e = blockIdx.x * blockDim.x + threadIdx.x;
    if (e >= Ee) return;
    atomicAdd(&g_cnt[ei[Ee + e]], 1);
}

__global__ void k_scan1() {
    __shared__ int sh[256];
    int t = threadIdx.x;
    int i = blockIdx.x * 256 + t;
    int v = (i < Nn) ? (g_cnt[i] + 1) : 0;
    sh[t] = v;
    __syncthreads();
#pragma unroll
    for (int o = 1; o < 256; o <<= 1) {
        int u = (t >= o) ? sh[t - o] : 0;
        __syncthreads();
        sh[t] += u;
        __syncthreads();
    }
    if (i < Nn) g_rowptr[i] = sh[t] - v;
    if (t == 255) g_bsum[blockIdx.x] = sh[255];
}

__global__ void k_scan2() {
    __shared__ int sh[256];
    int t = threadIdx.x;
    int v = (t < NB_SCAN) ? g_bsum[t] : 0;
    sh[t] = v;
    __syncthreads();
#pragma unroll
    for (int o = 1; o < 256; o <<= 1) {
        int u = (t >= o) ? sh[t - o] : 0;
        __syncthreads();
        sh[t] += u;
        __syncthreads();
    }
    if (t < NB_SCAN) g_boff[t] = sh[t] - v;
    if (t == 255) g_rowptr[Nn] = sh[255];
}

__global__ void k_scan3() {
    int i = blockIdx.x * 256 + threadIdx.x;
    if (i < Nn) g_rowptr[i] += g_boff[blockIdx.x];
}

// scatter psrc + permute edge_attr into CSR order
__global__ void k_scatter(const int* __restrict__ ei, const float* __restrict__ eattr) {
    int e = blockIdx.x * blockDim.x + threadIdx.x;
    if (e >= Ee) return;
    int s = ei[e], d = ei[Ee + e];
    int pos = g_rowptr[d] + atomicAdd(&g_fill[d], 1);
    g_psrc[pos] = s;
    const float4* sp = (const float4*)(eattr + (size_t)e * EDIM);
    float4* dp = (float4*)(g_pattr + (size_t)pos * EDIM);
    dp[0] = sp[0]; dp[1] = sp[1]; dp[2] = sp[2]; dp[3] = sp[3];
}

// per-node mean of real in-edge attrs -> self-loop slot; psrc self = n
__global__ void __launch_bounds__(256) k_meanattr() {
    int n = (blockIdx.x * 256 + threadIdx.x) >> 5;
    int lane = threadIdx.x & 31;
    if (n >= Nn) return;
    int s0 = g_rowptr[n], s1 = g_rowptr[n + 1] - 1;   // real edges [s0,s1)
    float4 acc = make_float4(0.f, 0.f, 0.f, 0.f);
    const float4* pa = (const float4*)g_pattr;
    for (int r = s0 + (lane >> 2); r < s1; r += 8) {
        float4 v = pa[(size_t)r * 4 + (lane & 3)];
        acc.x += v.x; acc.y += v.y; acc.z += v.z; acc.w += v.w;
    }
#pragma unroll
    for (int o = 4; o < 32; o <<= 1) {
        acc.x += __shfl_xor_sync(0xffffffffu, acc.x, o);
        acc.y += __shfl_xor_sync(0xffffffffu, acc.y, o);
        acc.z += __shfl_xor_sync(0xffffffffu, acc.z, o);
        acc.w += __shfl_xor_sync(0xffffffffu, acc.w, o);
    }
    if (lane < 4) {
        float ic = 1.0f / fmaxf((float)(s1 - s0), 1.0f);
        acc.x *= ic; acc.y *= ic; acc.z *= ic; acc.w *= ic;
        ((float4*)g_pattr)[(size_t)s1 * 4 + lane] = acc;
    }
    if (lane == 0) g_psrc[s1] = n;
}

// ---------------- per-layer ----------------
// GEMM + fused score epilogue; 2-stage cp.async double-buffered k-tiles.
template <int K>
__global__ void __launch_bounds__(128, 5) k_gemm(const float* __restrict__ A,
                                                 const float* __restrict__ W,
                                                 const float* __restrict__ a_s,
                                                 const float* __restrict__ a_d,
                                                 float* __restrict__ Out) {
    __shared__ float Ws[2][32][128];   // 32 KB
    __shared__ float Xs[2][32][32];    // 8 KB
    int tid = threadIdx.x;
    int tx = tid & 31, ty = tid >> 5;
    int rowbase = blockIdx.x * 32;
    float4 acc[8];
#pragma unroll
    for (int r = 0; r < 8; r++) acc[r] = make_float4(0.f, 0.f, 0.f, 0.f);

    auto load_tiles = [&](int s, int kc) {
#pragma unroll
        for (int q = 0; q < 8; q++) {
            int idx = tid + 128 * q;
            int r = idx >> 5, c4 = idx & 31;
            cpa16((unsigned int)__cvta_generic_to_shared(&Ws[s][r][c4 * 4]),
                  &W[(size_t)(kc + r) * HC + c4 * 4], 16);
        }
#pragma unroll
        for (int q = 0; q < 2; q++) {
            int idx = tid + 128 * q;
            int r = idx >> 3, c4 = idx & 7;
            int row = rowbase + r;
            int ok = (row < Nn) ? 16 : 0;
            int rowc = (row < Nn) ? row : 0;
            cpa16((unsigned int)__cvta_generic_to_shared(&Xs[s][r][c4 * 4]),
                  &A[(size_t)rowc * K + kc + c4 * 4], ok);
        }
    };

    constexpr int NIT = K / 32;
    load_tiles(0, 0);
    asm volatile("cp.async.commit_group;" ::: "memory");

#pragma unroll
    for (int it = 0; it < NIT; it++) {
        int buf = it & 1;
        if (it + 1 < NIT) {
            load_tiles(buf ^ 1, (it + 1) * 32);
            asm volatile("cp.async.commit_group;" ::: "memory");
            asm volatile("cp.async.wait_group 1;" ::: "memory");
        } else {
            asm volatile("cp.async.wait_group 0;" ::: "memory");
        }
        __syncthreads();
#pragma unroll
        for (int k4 = 0; k4 < 32; k4 += 4) {
            float4 a4[8];
#pragma unroll
            for (int r = 0; r < 8; r++) a4[r] = *(const float4*)&Xs[buf][ty + 4 * r][k4];
#pragma unroll
            for (int kk = 0; kk < 4; kk++) {
                float4 b4 = *(const float4*)&Ws[buf][k4 + kk][tx * 4];
#pragma unroll
                for (int r = 0; r < 8; r++) {
                    float a = (kk == 0) ? a4[r].x : (kk == 1) ? a4[r].y : (kk == 2) ? a4[r].z : a4[r].w;
                    acc[r].x += a * b4.x;
                    acc[r].y += a * b4.y;
                    acc[r].z += a * b4.z;
                    acc[r].w += a * b4.w;
                }
            }
        }
        __syncthreads();
    }

    float4 as4 = *(const float4*)&a_s[tx * 4];
    float4 ad4 = *(const float4*)&a_d[tx * 4];
    int head = tx >> 3;

#pragma unroll
    for (int r = 0; r < 8; r++) {
        int row = rowbase + ty + 4 * r;
        if (row < Nn) {
            *(float4*)&Out[(size_t)row * HC + tx * 4] = acc[r];
            float ps = acc[r].x * as4.x + acc[r].y * as4.y + acc[r].z * as4.z + acc[r].w * as4.w;
            float pd = acc[r].x * ad4.x + acc[r].y * ad4.y + acc[r].z * ad4.z + acc[r].w * ad4.w;
#pragma unroll
            for (int o = 1; o < 8; o <<= 1) {
                ps += __shfl_xor_sync(0xffffffffu, ps, o);
                pd += __shfl_xor_sync(0xffffffffu, pd, o);
            }
            if ((tx & 7) == 0) {
                g_scs[row * 4 + head] = ps;
                g_scd[row * 4 + head] = pd;
            }
        }
    }
}

// ALL THREE layers' edge scores in one pass over pattr (read 54MB once, not 3x)
__global__ void k_sce3(const float* __restrict__ We0, const float* __restrict__ ae0,
                       const float* __restrict__ We1, const float* __restrict__ ae1,
                       const float* __restrict__ We2, const float* __restrict__ ae2) {
    __shared__ float ve[3][EDIM * Hh];
    int t = threadIdx.x;
    if (t < 3 * EDIM * Hh) {
        int l = t >> 6, u = t & 63;
        int d = u >> 2, h = u & 3;
        const float* We = (l == 0) ? We0 : (l == 1) ? We1 : We2;
        const float* ae = (l == 0) ? ae0 : (l == 1) ? ae1 : ae2;
        float s = 0.f;
#pragma unroll
        for (int c = 0; c < Cc; c++) s += We[d * HC + h * Cc + c] * ae[h * Cc + c];
        ve[l][u] = s;
    }
    __syncthreads();
    int i = blockIdx.x * blockDim.x + threadIdx.x;
    if (i >= EF) return;
    const float* ap = g_pattr + (size_t)i * EDIM;
    float4 av[4];
#pragma unroll
    for (int q = 0; q < 4; q++) av[q] = *(const float4*)(ap + q * 4);
#pragma unroll
    for (int l = 0; l < 3; l++) {
        const float* v = ve[l];
        float h0 = 0.f, h1 = 0.f, h2 = 0.f, h3 = 0.f;
#pragma unroll
        for (int q = 0; q < 4; q++) {
            int d = q * 4;
            h0 += av[q].x * v[d * 4 + 0] + av[q].y * v[(d + 1) * 4 + 0] + av[q].z * v[(d + 2) * 4 + 0] + av[q].w * v[(d + 3) * 4 + 0];
            h1 += av[q].x * v[d * 4 + 1] + av[q].y * v[(d + 1) * 4 + 1] + av[q].z * v[(d + 2) * 4 + 1] + av[q].w * v[(d + 3) * 4 + 1];
            h2 += av[q].x * v[d * 4 + 2] + av[q].y * v[(d + 1) * 4 + 2] + av[q].z * v[(d + 2) * 4 + 2] + av[q].w * v[(d + 3) * 4 + 2];
            h3 += av[q].x * v[d * 4 + 3] + av[q].y * v[(d + 1) * 4 + 3] + av[q].z * v[(d + 2) * 4 + 3] + av[q].w * v[(d + 3) * 4 + 3];
        }
        *(float4*)(g_sce + ((size_t)l * EF + i) * 4) = make_float4(h0, h1, h2, h3);
    }
}

// pick this lane's head weight from edge j's float4 weights (deg>32 fallback)
__device__ __forceinline__ float head_w(float4 wv, int j, int lane) {
    float wx = __shfl_sync(0xffffffffu, wv.x, j);
    float wy = __shfl_sync(0xffffffffu, wv.y, j);
    float wz = __shfl_sync(0xffffffffu, wv.z, j);
    float ww = __shfl_sync(0xffffffffu, wv.w, j);
    return lane < 16 ? (lane < 8 ? wx : wy) : (lane < 24 ? wz : ww);
}

__global__ void __launch_bounds__(256) k_agg(const float* __restrict__ xw,
                                             const float* __restrict__ sce,
                                             const float* __restrict__ bias,
                                             float* __restrict__ hout) {
    __shared__ int   s_src[8][32];
    __shared__ float s_w[8][32][4];
    int wid = threadIdx.x >> 5;
    int n = (blockIdx.x * 256 + threadIdx.x) >> 5;
    int lane = threadIdx.x & 31;
    if (n >= Nn) return;
    int s0 = g_rowptr[n], s1 = g_rowptr[n + 1];
    int deg = s1 - s0;
    float4 sd = *(const float4*)(g_scd + n * 4);
    float4 acc = make_float4(0.f, 0.f, 0.f, 0.f);

    if (deg <= 32) {
        int e = s0 + lane;
        bool v = e < s1;
        int srcv = 0;
        float4 raw = make_float4(-FLT_MAX, -FLT_MAX, -FLT_MAX, -FLT_MAX);
        if (v) {
            srcv = g_psrc[e];
            raw = raw_score(sce, srcv, e, sd);
        }
        float4 m = wmax4(raw);
        float4 a = make_float4(0.f, 0.f, 0.f, 0.f);
        if (v) {
            a.x = __expf(raw.x - m.x);
            a.y = __expf(raw.y - m.y);
            a.z = __expf(raw.z - m.z);
            a.w = __expf(raw.w - m.w);
        }
        float4 s = wsum4(a);
        s_src[wid][lane] = srcv;
        s_w[wid][lane][0] = a.x / (s.x + 1e-16f);
        s_w[wid][lane][1] = a.y / (s.y + 1e-16f);
        s_w[wid][lane][2] = a.z / (s.z + 1e-16f);
        s_w[wid][lane][3] = a.w / (s.w + 1e-16f);
        __syncwarp();

        int c = lane >> 3;
        int j = 0;
        for (; j + 4 <= deg; j += 4) {
            int sj0 = s_src[wid][j],     sj1 = s_src[wid][j + 1];
            int sj2 = s_src[wid][j + 2], sj3 = s_src[wid][j + 3];
            float w0 = s_w[wid][j][c],     w1 = s_w[wid][j + 1][c];
            float w2 = s_w[wid][j + 2][c], w3 = s_w[wid][j + 3][c];
            float4 x0 = *(const float4*)(xw + (size_t)sj0 * HC + lane * 4);
            float4 x1 = *(const float4*)(xw + (size_t)sj1 * HC + lane * 4);
            float4 x2 = *(const float4*)(xw + (size_t)sj2 * HC + lane * 4);
            float4 x3 = *(const float4*)(xw + (size_t)sj3 * HC + lane * 4);
            acc.x += w0 * x0.x + w1 * x1.x + w2 * x2.x + w3 * x3.x;
            acc.y += w0 * x0.y + w1 * x1.y + w2 * x2.y + w3 * x3.y;
            acc.z += w0 * x0.z + w1 * x1.z + w2 * x2.z + w3 * x3.z;
            acc.w += w0 * x0.w + w1 * x1.w + w2 * x2.w + w3 * x3.w;
        }
        for (; j < deg; j++) {
            int sj = s_src[wid][j];
            float wj = s_w[wid][j][c];
            float4 xr = *(const float4*)(xw + (size_t)sj * HC + lane * 4);
            acc.x += wj * xr.x;
            acc.y += wj * xr.y;
            acc.z += wj * xr.z;
            acc.w += wj * xr.w;
        }
    } else {
        float4 pm = make_float4(-FLT_MAX, -FLT_MAX, -FLT_MAX, -FLT_MAX);
        for (int base = s0; base < s1; base += 32) {
            int e = base + lane;
            if (e < s1) {
                float4 raw = raw_score(sce, g_psrc[e], e, sd);
                pm.x = fmaxf(pm.x, raw.x); pm.y = fmaxf(pm.y, raw.y);
                pm.z = fmaxf(pm.z, raw.z); pm.w = fmaxf(pm.w, raw.w);
            }
        }
        float4 m = wmax4(pm);
        float4 ps = make_float4(0.f, 0.f, 0.f, 0.f);
        for (int base = s0; base < s1; base += 32) {
            int e = base + lane;
            if (e < s1) {
                float4 raw = raw_score(sce, g_psrc[e], e, sd);
                ps.x += __expf(raw.x - m.x);
                ps.y += __expf(raw.y - m.y);
                ps.z += __expf(raw.z - m.z);
                ps.w += __expf(raw.w - m.w);
            }
        }
        float4 s = wsum4(ps);
        float4 rinv;
        rinv.x = 1.f / (s.x + 1e-16f);
        rinv.y = 1.f / (s.y + 1e-16f);
        rinv.z = 1.f / (s.z + 1e-16f);
        rinv.w = 1.f / (s.w + 1e-16f);
        for (int base = s0; base < s1; base += 32) {
            int e = base + lane;
            int sv = 0;
            float4 wv = make_float4(0.f, 0.f, 0.f, 0.f);
            if (e < s1) {
                sv = g_psrc[e];
                float4 raw = raw_score(sce, sv, e, sd);
                wv.x = __expf(raw.x - m.x) * rinv.x;
                wv.y = __expf(raw.y - m.y) * rinv.y;
                wv.z = __expf(raw.z - m.z) * rinv.z;
                wv.w = __expf(raw.w - m.w) * rinv.w;
            }
            int c2 = s1 - base; if (c2 > 32) c2 = 32;
            for (int j = 0; j < c2; j++) {
                int sj = __shfl_sync(0xffffffffu, sv, j);
                float wsel = head_w(wv, j, lane);
                float4 xr = *(const float4*)(xw + (size_t)sj * HC + lane * 4);
                acc.x += wsel * xr.x;
                acc.y += wsel * xr.y;
                acc.z += wsel * xr.z;
                acc.w += wsel * xr.w;
            }
        }
    }
    float4 b4 = *(const float4*)(bias + lane * 4);
    float4 o4;
    o4.x = fmaxf(acc.x + b4.x, 0.f);
    o4.y = fmaxf(acc.y + b4.y, 0.f);
    o4.z = fmaxf(acc.z + b4.z, 0.f);
    o4.w = fmaxf(acc.w + b4.w, 0.f);
    *(float4*)(hout + (size_t)n * HC + lane * 4) = o4;
}

// ---------------- output head ----------------
__global__ void __launch_bounds__(128) k_pool(const float* __restrict__ h,
                                              const int* __restrict__ batch) {
    int t = threadIdx.x;
    int n0 = blockIdx.x * 64;
    int nend = n0 + 64; if (nend > Nn) nend = Nn;
    float acc = 0.f;
    int cnt = 0;
    int curb = batch[n0];
    for (int n = n0; n < nend; n++) {
        int b = batch[n];
        if (b != curb) {
            atomicAdd(&g_gsum[curb * HC + t], acc);
            if (t == 0) atomicAdd(&g_gcnt[curb], cnt);
            curb = b; acc = 0.f; cnt = 0;
        }
        acc += h[(size_t)n * HC + t];
        cnt++;
    }
    atomicAdd(&g_gsum[curb * HC + t], acc);
    if (t == 0) atomicAdd(&g_gcnt[curb], cnt);
}

__global__ void k_head(const float* __restrict__ Wl, const float* __restrict__ bl,
                       float* __restrict__ out) {
    int tid = threadIdx.x;
    if (tid >= Bb * Aa) return;
    int b = tid >> 3, a = tid & 7;
    float ic = 1.0f / fmaxf((float)g_gcnt[b], 1.0f);
    float s = 0.f;
    for (int c = 0; c < HC; c++) s += g_gsum[b * HC + c] * Wl[c * Aa + a];
    out[tid] = tanhf(s * ic + bl[a]);
}

// ---------------- launch ----------------
extern "C" void kernel_launch(void* const* d_in, const int* in_sizes, int n_in,
                              void* d_out, int out_size) {
    const float* slots[22];
    int k = 0;
    const int* ei = nullptr;
    const int* batch = nullptr;
    for (int i = 0; i < n_in; i++) {
        int sz = in_sizes[i];
        if (sz == 2 * Ee) ei = (const int*)d_in[i];
        else if (sz == Nn) batch = (const int*)d_in[i];
        else if (k < 22) slots[k++] = (const float*)d_in[i];
    }
    const float* x      = slots[0];
    const float* eattr  = slots[1];
    const float* W[3]   = { slots[2],  slots[8],  slots[14] };
    const float* We[3]  = { slots[3],  slots[9],  slots[15] };
    const float* aS[3]  = { slots[4],  slots[10], slots[16] };
    const float* aD[3]  = { slots[5],  slots[11], slots[17] };
    const float* aE[3]  = { slots[6],  slots[12], slots[18] };
    const float* bia[3] = { slots[7],  slots[13], slots[19] };
    const float* Wl = slots[20];
    const float* bl = slots[21];
    float* out = (float*)d_out;

    float *p_xw, *p_hA, *p_hB, *p_sce;
    cudaGetSymbolAddress((void**)&p_xw, g_xw);
    cudaGetSymbolAddress((void**)&p_hA, g_hA);
    cudaGetSymbolAddress((void**)&p_hB, g_hB);
    cudaGetSymbolAddress((void**)&p_sce, g_sce);

    k_init<<<(Nn + 255) / 256, 256>>>();
    k_count<<<(Ee + 255) / 256, 256>>>(ei);
    k_scan1<<<NB_SCAN, 256>>>();
    // launch #4 -> profiled by the fixed ncu window; verify cp.async pipeline effect
    k_gemm<64><<<(Nn + 31) / 32, 128>>>(x, W[0], aS[0], aD[0], p_xw);
    k_scan2<<<1, 256>>>();
    k_scan3<<<NB_SCAN, 256>>>();
    k_scatter<<<(Ee + 255) / 256, 256>>>(ei, eattr);
    k_meanattr<<<(Nn * 32 + 255) / 256, 256>>>();
    k_sce3<<<(EF + 255) / 256, 256>>>(We[0], aE[0], We[1], aE[1], We[2], aE[2]);

    const float* hin = x;
    float* houts[3] = { p_hA, p_hB, p_hA };
    for (int l = 0; l < 3; l++) {
        if (l > 0) k_gemm<128><<<(Nn + 31) / 32, 128>>>(hin, W[l], aS[l], aD[l], p_xw);
        k_agg<<<(Nn + 7) / 8, 256>>>(p_xw, p_sce + (size_t)l * EF * Hh, bia[l], houts[l]);
        hin = houts[l];
    }

    k_pool<<<(Nn + 63) / 64, 128>>>(hin, batch);
    k_head<<<1, 512>>>(Wl, bl, out);
}